// round 5
// baseline (speedup 1.0000x reference)
#include <cuda_runtime.h>
#include <cuda_fp16.h>
#include <cstdint>

#define NLVL  10
#define EMB   64
#define NROWS 10002   // 2 zero rows + 10000 table rows

__device__ __align__(16)  float  g_ew[12];             // exp(w[l]); [10],[11]=0
__device__ __align__(256) __half g_tab[NROWS * EMB];   // fp16 concept_emb_cat, row=128B

// Convert table fp32->fp16 (rows shifted by +2, rows 0/1 zeroed) and exp(w).
// 8 floats per thread.
__global__ void conv_kernel(const float* __restrict__ emb,
                            const float* __restrict__ w, int n8) {
    const int tid = blockIdx.x * blockDim.x + threadIdx.x;
    if (blockIdx.x == 0) {
        if (threadIdx.x < 12)
            g_ew[threadIdx.x] = (threadIdx.x < NLVL) ? __expf(w[threadIdx.x]) : 0.0f;
        if (threadIdx.x < 16)   // zero rows 0,1: 256B = 16 x 16B
            reinterpret_cast<uint4*>(g_tab)[threadIdx.x] = make_uint4(0u,0u,0u,0u);
    }
    if (tid < n8) {
        const float4 a = *reinterpret_cast<const float4*>(emb + (size_t)tid * 8);
        const float4 b = *reinterpret_cast<const float4*>(emb + (size_t)tid * 8 + 4);
        const __half2 h0 = __floats2half2_rn(a.x, a.y);
        const __half2 h1 = __floats2half2_rn(a.z, a.w);
        const __half2 h2 = __floats2half2_rn(b.x, b.y);
        const __half2 h3 = __floats2half2_rn(b.z, b.w);
        uint4 p;
        p.x = *reinterpret_cast<const unsigned*>(&h0);
        p.y = *reinterpret_cast<const unsigned*>(&h1);
        p.z = *reinterpret_cast<const unsigned*>(&h2);
        p.w = *reinterpret_cast<const unsigned*>(&h3);
        *reinterpret_cast<uint4*>(g_tab + 2 * EMB + (size_t)tid * 8) = p;
    }
}

// Quarter-warp (8 lanes) per token; lane qi covers cols [8*qi, 8*qi+8).
// Each gather is LDG.128: one warp instruction serves 4 tokens (4 L1 lines).
__global__ __launch_bounds__(256, 3) void kcroute_kernel(
    const int* __restrict__ croutes,   // [ntok, NLVL]
    float*     __restrict__ out,       // [ntok, EMB]
    int ntok)
{
    const int gtid = blockIdx.x * blockDim.x + threadIdx.x;
    const int tok  = gtid >> 3;
    const int qi   = gtid & 7;
    if (tok >= ntok) return;

    // Indices: 5x LDG.64, broadcast within the 8-lane group.
    const int2* cr = reinterpret_cast<const int2*>(croutes + (size_t)tok * NLVL);
    const int2 i0 = __ldg(cr + 0), i1 = __ldg(cr + 1), i2 = __ldg(cr + 2),
               i3 = __ldg(cr + 3), i4 = __ldg(cr + 4);
    const int idx[NLVL] = { i0.x, i0.y, i1.x, i1.y, i2.x, i2.y,
                            i3.x, i3.y, i4.x, i4.y };

    // All 10 gathers back-to-back, unconditional (zero rows absorb -1/-2). MLP=10.
    uint4 v[NLVL];
#pragma unroll
    for (int l = 0; l < NLVL; l++) {
        v[l] = *reinterpret_cast<const uint4*>(
            g_tab + ((size_t)(idx[l] + 2)) * EMB + qi * 8);
    }

    // Precomputed exp(w): 3 broadcast loads (L1/L2 resident).
    const float4 ea = *reinterpret_cast<const float4*>(&g_ew[0]);
    const float4 eb = *reinterpret_cast<const float4*>(&g_ew[4]);
    const float2 ec = *reinterpret_cast<const float2*>(&g_ew[8]);
    const float e[NLVL] = { ea.x, ea.y, ea.z, ea.w,
                            eb.x, eb.y, eb.z, eb.w, ec.x, ec.y };

    // Denominator: level available iff croutes != -2 (croutes == -1 gathers the
    // zero row, matching the reference).
    float s = 0.0f;
#pragma unroll
    for (int l = 0; l < NLVL; l++) s += (idx[l] != -2) ? e[l] : 0.0f;
    const float inv = (s > 0.0f) ? __frcp_rn(s) : 0.0f;

    float acc[8] = {0.f,0.f,0.f,0.f,0.f,0.f,0.f,0.f};
#pragma unroll
    for (int l = 0; l < NLVL; l++) {
        const float2 a = __half22float2(*reinterpret_cast<const __half2*>(&v[l].x));
        const float2 b = __half22float2(*reinterpret_cast<const __half2*>(&v[l].y));
        const float2 c = __half22float2(*reinterpret_cast<const __half2*>(&v[l].z));
        const float2 d = __half22float2(*reinterpret_cast<const __half2*>(&v[l].w));
        acc[0] = fmaf(e[l], a.x, acc[0]);
        acc[1] = fmaf(e[l], a.y, acc[1]);
        acc[2] = fmaf(e[l], b.x, acc[2]);
        acc[3] = fmaf(e[l], b.y, acc[3]);
        acc[4] = fmaf(e[l], c.x, acc[4]);
        acc[5] = fmaf(e[l], c.y, acc[5]);
        acc[6] = fmaf(e[l], d.x, acc[6]);
        acc[7] = fmaf(e[l], d.y, acc[7]);
    }

    float* op = out + (size_t)tok * EMB + qi * 8;
    float4 o0 = make_float4(acc[0]*inv, acc[1]*inv, acc[2]*inv, acc[3]*inv);
    float4 o1 = make_float4(acc[4]*inv, acc[5]*inv, acc[6]*inv, acc[7]*inv);
    *reinterpret_cast<float4*>(op)     = o0;
    *reinterpret_cast<float4*>(op + 4) = o1;
}

extern "C" void kernel_launch(void* const* d_in, const int* in_sizes, int n_in,
                              void* d_out, int out_size) {
    const int*   croutes = (const int*)d_in[0];
    // d_in[1] (tailcs) unused by the reference computation.
    const float* emb     = (const float*)d_in[2];
    const float* w       = (const float*)d_in[3];
    float*       out     = (float*)d_out;

    const int ntok = in_sizes[1];                 // B * S
    const int n8   = in_sizes[2] / 8;             // table 8-float chunks
    conv_kernel<<<(n8 + 255) / 256, 256>>>(emb, w, n8);

    const int blocks = (ntok * 8 + 255) / 256;    // 32 tokens per block
    kcroute_kernel<<<blocks, 256>>>(croutes, out, ntok);
}

// round 6
// speedup vs baseline: 1.0194x; 1.0194x over previous
#include <cuda_runtime.h>
#include <cuda_fp16.h>
#include <cstdint>

#define NLVL  10
#define EMB   64
#define NROWS 10002    // 2 zero rows + 10000 table rows
#define TOK   32       // tokens per block
#define ROWP  12       // padded smem row (ints/floats), 48B -> 16B-aligned rows

__device__ __align__(16)  float  g_ew[12];             // exp(w[l]); [10],[11]=0
__device__ __align__(256) __half g_tab[NROWS * EMB];   // fp16 concept_emb_cat, row=128B

// Convert table fp32->fp16 (rows shifted by +2, rows 0/1 zeroed) and exp(w).
__global__ void conv_kernel(const float* __restrict__ emb,
                            const float* __restrict__ w, int n8) {
    const int tid = blockIdx.x * blockDim.x + threadIdx.x;
    if (blockIdx.x == 0) {
        if (threadIdx.x < 12)
            g_ew[threadIdx.x] = (threadIdx.x < NLVL) ? __expf(w[threadIdx.x]) : 0.0f;
        if (threadIdx.x < 16)   // zero rows 0,1: 256B = 16 x 16B
            reinterpret_cast<uint4*>(g_tab)[threadIdx.x] = make_uint4(0u,0u,0u,0u);
    }
    if (tid < n8) {
        const float4 a = *reinterpret_cast<const float4*>(emb + (size_t)tid * 8);
        const float4 b = *reinterpret_cast<const float4*>(emb + (size_t)tid * 8 + 4);
        const __half2 h0 = __floats2half2_rn(a.x, a.y);
        const __half2 h1 = __floats2half2_rn(a.z, a.w);
        const __half2 h2 = __floats2half2_rn(b.x, b.y);
        const __half2 h3 = __floats2half2_rn(b.z, b.w);
        uint4 p;
        p.x = *reinterpret_cast<const unsigned*>(&h0);
        p.y = *reinterpret_cast<const unsigned*>(&h1);
        p.z = *reinterpret_cast<const unsigned*>(&h2);
        p.w = *reinterpret_cast<const unsigned*>(&h3);
        *reinterpret_cast<uint4*>(g_tab + 2 * EMB + (size_t)tid * 8) = p;
    }
}

// 32 tokens per 256-thread block. Phase 1: coalesced idx load + per-token
// prenormalized softmax into smem. Phase 2: 8 lanes/token, LDG.128 gathers.
__global__ __launch_bounds__(256, 4) void kcroute_kernel(
    const int* __restrict__ croutes,   // [ntok, NLVL]
    float*     __restrict__ out,       // [ntok, EMB]
    int ntok)
{
    __shared__ int   si[TOK][ROWP];   // indices
    __shared__ float sa[TOK][ROWP];   // prenormalized alphas; [10],[11]=0

    const int tid      = threadIdx.x;
    const int blk_tok0 = blockIdx.x * TOK;

    // ---- Phase 1a: 80 threads load 320 indices as int4 (fully coalesced) ----
    if (tid < TOK * NLVL / 4) {
        const int f = tid * 4;
        int4 r = make_int4(-2, -2, -2, -2);
        const size_t g = (size_t)blk_tok0 * NLVL + f;
        if ((int)(g / NLVL) < ntok || blk_tok0 + TOK <= ntok)  // full block fast path
            r = *reinterpret_cast<const int4*>(croutes + g);
#pragma unroll
        for (int k = 0; k < 4; k++) {
            const int fk = f + k;
            const int t  = fk / NLVL;
            const int l  = fk - t * NLVL;
            const int vv = (&r.x)[k];
            si[t][l] = vv;
        }
    }
    __syncthreads();

    // ---- Phase 1b: one thread per token computes prenormalized alphas ----
    if (tid < TOK) {
        const int4 ia = *reinterpret_cast<const int4*>(&si[tid][0]);
        const int4 ib = *reinterpret_cast<const int4*>(&si[tid][4]);
        const int2 ic = *reinterpret_cast<const int2*>(&si[tid][8]);
        const int idx[NLVL] = { ia.x, ia.y, ia.z, ia.w,
                                ib.x, ib.y, ib.z, ib.w, ic.x, ic.y };
        const float4 ea = *reinterpret_cast<const float4*>(&g_ew[0]);
        const float4 eb = *reinterpret_cast<const float4*>(&g_ew[4]);
        const float2 ec = *reinterpret_cast<const float2*>(&g_ew[8]);
        const float e[NLVL] = { ea.x, ea.y, ea.z, ea.w,
                                eb.x, eb.y, eb.z, eb.w, ec.x, ec.y };
        float s = 0.0f;
#pragma unroll
        for (int l = 0; l < NLVL; l++) s += (idx[l] != -2) ? e[l] : 0.0f;
        const float inv = (s > 0.0f) ? __frcp_rn(s) : 0.0f;
#pragma unroll
        for (int l = 0; l < NLVL; l++)
            sa[tid][l] = (idx[l] != -2) ? e[l] * inv : 0.0f;
        sa[tid][10] = 0.0f;
        sa[tid][11] = 0.0f;
    }
    __syncthreads();

    // ---- Phase 2: gather + combine. 8 lanes per token, LDG.128 each. ----
    const int t    = tid >> 3;          // local token
    const int qi   = tid & 7;           // covers cols [8*qi, 8*qi+8)
    const int gtok = blk_tok0 + t;

    const int4 ia = *reinterpret_cast<const int4*>(&si[t][0]);
    const int4 ib = *reinterpret_cast<const int4*>(&si[t][4]);
    const int2 ic = *reinterpret_cast<const int2*>(&si[t][8]);
    const int idx[NLVL] = { ia.x, ia.y, ia.z, ia.w,
                            ib.x, ib.y, ib.z, ib.w, ic.x, ic.y };

    // All 10 gathers back-to-back (zero rows absorb croutes in {-1,-2}). MLP=10.
    uint4 v[NLVL];
#pragma unroll
    for (int l = 0; l < NLVL; l++) {
        v[l] = *reinterpret_cast<const uint4*>(
            g_tab + ((size_t)(idx[l] + 2)) * EMB + qi * 8);
    }

    const float4 aa = *reinterpret_cast<const float4*>(&sa[t][0]);
    const float4 ab = *reinterpret_cast<const float4*>(&sa[t][4]);
    const float2 ac = *reinterpret_cast<const float2*>(&sa[t][8]);
    const float al[NLVL] = { aa.x, aa.y, aa.z, aa.w,
                             ab.x, ab.y, ab.z, ab.w, ac.x, ac.y };

    float acc[8] = {0.f,0.f,0.f,0.f,0.f,0.f,0.f,0.f};
#pragma unroll
    for (int l = 0; l < NLVL; l++) {
        const float2 a = __half22float2(*reinterpret_cast<const __half2*>(&v[l].x));
        const float2 b = __half22float2(*reinterpret_cast<const __half2*>(&v[l].y));
        const float2 c = __half22float2(*reinterpret_cast<const __half2*>(&v[l].z));
        const float2 d = __half22float2(*reinterpret_cast<const __half2*>(&v[l].w));
        acc[0] = fmaf(al[l], a.x, acc[0]);
        acc[1] = fmaf(al[l], a.y, acc[1]);
        acc[2] = fmaf(al[l], b.x, acc[2]);
        acc[3] = fmaf(al[l], b.y, acc[3]);
        acc[4] = fmaf(al[l], c.x, acc[4]);
        acc[5] = fmaf(al[l], c.y, acc[5]);
        acc[6] = fmaf(al[l], d.x, acc[6]);
        acc[7] = fmaf(al[l], d.y, acc[7]);
    }

    if (gtok < ntok) {
        float* op = out + (size_t)gtok * EMB + qi * 8;
        *reinterpret_cast<float4*>(op)     = make_float4(acc[0], acc[1], acc[2], acc[3]);
        *reinterpret_cast<float4*>(op + 4) = make_float4(acc[4], acc[5], acc[6], acc[7]);
    }
}

extern "C" void kernel_launch(void* const* d_in, const int* in_sizes, int n_in,
                              void* d_out, int out_size) {
    const int*   croutes = (const int*)d_in[0];
    // d_in[1] (tailcs) unused by the reference computation.
    const float* emb     = (const float*)d_in[2];
    const float* w       = (const float*)d_in[3];
    float*       out     = (float*)d_out;

    const int ntok = in_sizes[1];                 // B * S
    const int n8   = in_sizes[2] / 8;             // table 8-float chunks
    conv_kernel<<<(n8 + 255) / 256, 256>>>(emb, w, n8);

    const int blocks = (ntok + TOK - 1) / TOK;
    kcroute_kernel<<<blocks, 256>>>(croutes, out, ntok);
}